// round 2
// baseline (speedup 1.0000x reference)
#include <cuda_runtime.h>
#include <cstdint>

#define NAB       128
#define NG        50
#define NG_PAD    52
#define EB        8
#define MAX_ATOMS 50000

// Scratch (allocation-free): rf and agg, 25.6 MB each.
__device__ __align__(16) float g_rf[(size_t)MAX_ATOMS * NAB];
__device__ __align__(16) float g_agg[(size_t)MAX_ATOMS * NAB];

__device__ __forceinline__ float sspf(float x) {
    // softplus(x) - ln(2), numerically stable
    return fmaxf(x, 0.0f) + log1pf(__expf(-fabsf(x))) - 0.6931471805599453f;
}

// ---------------------------------------------------------------------------
// rf = r @ W_af   (warp-per-row-pair, W_af L1/L2-resident)
// ---------------------------------------------------------------------------
__global__ void __launch_bounds__(128) k_rf(const float* __restrict__ r,
                                            const float* __restrict__ Waf,
                                            int Nrows) {
    __shared__ __align__(16) float s_row[4][2][NAB];
    int w = threadIdx.x >> 5, l = threadIdx.x & 31;
    int f4 = l * 4;
    int npairs = (Nrows + 1) >> 1;
    for (int pair = blockIdx.x * 4 + w; pair < npairs; pair += gridDim.x * 4) {
        int r0 = pair * 2;
        int r1 = r0 + 1;
        bool has1 = (r1 < Nrows);
        *(float4*)&s_row[w][0][f4] = *(const float4*)&r[(size_t)r0 * NAB + f4];
        *(float4*)&s_row[w][1][f4] = has1 ? *(const float4*)&r[(size_t)r1 * NAB + f4]
                                          : make_float4(0.f, 0.f, 0.f, 0.f);
        __syncwarp();
        float4 a0 = make_float4(0.f, 0.f, 0.f, 0.f), a1 = a0;
        #pragma unroll 8
        for (int k = 0; k < NAB; k++) {
            float4 wv = __ldg((const float4*)&Waf[k * NAB + f4]);
            float x0 = s_row[w][0][k], x1 = s_row[w][1][k];
            a0.x += x0 * wv.x; a0.y += x0 * wv.y; a0.z += x0 * wv.z; a0.w += x0 * wv.w;
            a1.x += x1 * wv.x; a1.y += x1 * wv.y; a1.z += x1 * wv.z; a1.w += x1 * wv.w;
        }
        *(float4*)&g_rf[(size_t)r0 * NAB + f4] = a0;
        if (has1) *(float4*)&g_rf[(size_t)r1 * NAB + f4] = a1;
        __syncwarp();
    }
}

// ---------------------------------------------------------------------------
// Fused edge kernel: g -> h1 -> ef -> gather rf -> float4 atomics into agg
// 8 edges per tile, 128 threads/block, weights in SMEM.
// ---------------------------------------------------------------------------
__global__ void __launch_bounds__(128) k_edge(const float* __restrict__ e_arr,
                                              const int* __restrict__ a_arr,
                                              const float* __restrict__ W1g,
                                              const float* __restrict__ b1g,
                                              const float* __restrict__ W2g,
                                              const float* __restrict__ b2g,
                                              int E) {
    __shared__ __align__(16) float sW1[NG * NG_PAD];   // [i][j], padded rows
    __shared__ __align__(16) float sb1[64];
    __shared__ __align__(16) float sW2[NG * NAB];      // [j][f]
    __shared__ __align__(16) float sb2[NAB];
    __shared__ __align__(16) float s_g[EB * NG];       // [edge][i]
    __shared__ __align__(16) float s_h1[NG * EB];      // [j][edge]
    __shared__ __align__(16) float s_ev[EB];
    __shared__ int   s_src[EB], s_dst[EB];

    const int tid = threadIdx.x;

    // one-time weight staging
    for (int idx = tid; idx < NG * NG; idx += 128)
        sW1[(idx / NG) * NG_PAD + (idx % NG)] = W1g[idx];
    if (tid < 64) sb1[tid] = (tid < NG) ? b1g[tid] : 0.0f;
    for (int idx = tid; idx < NG * NAB; idx += 128) sW2[idx] = W2g[idx];
    sb2[tid] = b2g[tid];

    const float kWidth = 5.0f / 49.0f;                 // CUTOFF/(NG-1)
    const float kCoeff = -0.5f / (kWidth * kWidth);

    const int w  = tid >> 5;
    const int l  = tid & 31;
    const int el = l & 3;          // edge lane (0..3); also handles el+4
    const int jg = l >> 2;         // 0..7
    const int fb = w * 32 + jg * 4; // phase-C feature base (covers 0..124)

    const int ntiles = (E + EB - 1) / EB;
    for (int tile = blockIdx.x; tile < ntiles; tile += gridDim.x) {
        const int e0 = tile * EB;
        __syncthreads();           // protect shared reuse (also covers staging)
        if (tid < EB) {
            int ei = e0 + tid;
            if (ei < E) {
                s_ev[tid]  = e_arr[ei];
                s_src[tid] = a_arr[2 * (size_t)ei];
                s_dst[tid] = a_arr[2 * (size_t)ei + 1];
            } else {
                s_ev[tid] = 0.0f; s_src[tid] = -1; s_dst[tid] = -1;
            }
        }
        __syncthreads();

        // phase A: Gaussians
        for (int item = tid; item < EB * NG; item += 128) {
            int i  = item >> 3;
            int ee = item & 7;
            float d = s_ev[ee] - (float)i * kWidth;
            s_g[ee * NG + i] = __expf(kCoeff * d * d);
        }
        __syncthreads();

        // phase B: h1 = ssp(g @ W_df1 + b_df1), stored [j][edge]
        #pragma unroll
        for (int iter = 0; iter < 2; iter++) {
            int j4 = jg * 4 + iter * 32;
            if (j4 < NG) {
                float4 a  = make_float4(sb1[j4], sb1[j4 + 1], sb1[j4 + 2], sb1[j4 + 3]);
                float4 a2 = a;
                #pragma unroll 10
                for (int i = 0; i < NG; i++) {
                    float g1 = s_g[el * NG + i];
                    float g2 = s_g[(el + 4) * NG + i];
                    float4 wv = *(const float4*)&sW1[i * NG_PAD + j4];
                    a.x  += g1 * wv.x; a.y  += g1 * wv.y; a.z  += g1 * wv.z; a.w  += g1 * wv.w;
                    a2.x += g2 * wv.x; a2.y += g2 * wv.y; a2.z += g2 * wv.z; a2.w += g2 * wv.w;
                }
                float* pa  = (float*)&a;
                float* pa2 = (float*)&a2;
                #pragma unroll
                for (int k = 0; k < 4; k++) {
                    int j = j4 + k;
                    if (j < NG) {
                        s_h1[j * EB + el]     = sspf(pa[k]);
                        s_h1[j * EB + el + 4] = sspf(pa2[k]);
                    }
                }
            }
        }
        __syncthreads();

        // phase C: ef = h1 @ W_df2 + b_df2; gather rf; float4 atomics
        {
            float4 acc  = make_float4(sb2[fb], sb2[fb + 1], sb2[fb + 2], sb2[fb + 3]);
            float4 acc2 = acc;
            #pragma unroll 10
            for (int j = 0; j < NG; j++) {
                float h1 = s_h1[j * EB + el];
                float h2 = s_h1[j * EB + el + 4];
                float4 wv = *(const float4*)&sW2[j * NAB + fb];
                acc.x  += h1 * wv.x; acc.y  += h1 * wv.y; acc.z  += h1 * wv.z; acc.w  += h1 * wv.w;
                acc2.x += h2 * wv.x; acc2.y += h2 * wv.y; acc2.z += h2 * wv.z; acc2.w += h2 * wv.w;
            }
            int s1 = s_src[el], d1 = s_dst[el];
            if (s1 >= 0) {
                float4 rs = __ldg((const float4*)&g_rf[(size_t)s1 * NAB + fb]);
                float4 rd = __ldg((const float4*)&g_rf[(size_t)d1 * NAB + fb]);
                float4 m1 = make_float4(rs.x * acc.x, rs.y * acc.y, rs.z * acc.z, rs.w * acc.w);
                float4 m2 = make_float4(rd.x * acc.x, rd.y * acc.y, rd.z * acc.z, rd.w * acc.w);
                atomicAdd((float4*)&g_agg[(size_t)d1 * NAB + fb], m1);
                atomicAdd((float4*)&g_agg[(size_t)s1 * NAB + fb], m2);
            }
            int s2 = s_src[el + 4], d2 = s_dst[el + 4];
            if (s2 >= 0) {
                float4 rs = __ldg((const float4*)&g_rf[(size_t)s2 * NAB + fb]);
                float4 rd = __ldg((const float4*)&g_rf[(size_t)d2 * NAB + fb]);
                float4 m1 = make_float4(rs.x * acc2.x, rs.y * acc2.y, rs.z * acc2.z, rs.w * acc2.w);
                float4 m2 = make_float4(rd.x * acc2.x, rd.y * acc2.y, rd.z * acc2.z, rd.w * acc2.w);
                atomicAdd((float4*)&g_agg[(size_t)d2 * NAB + fb], m1);
                atomicAdd((float4*)&g_agg[(size_t)s2 * NAB + fb], m2);
            }
        }
    }
}

// ---------------------------------------------------------------------------
// out = ssp(agg @ W_d1 + b_d1) @ W_d2 + b_d2  (warp-per-row-pair)
// ---------------------------------------------------------------------------
__global__ void __launch_bounds__(128) k_out(const float* __restrict__ W1,
                                             const float* __restrict__ b1,
                                             const float* __restrict__ W2,
                                             const float* __restrict__ b2,
                                             float* __restrict__ out,
                                             int Nrows) {
    __shared__ __align__(16) float s_row[4][2][NAB];
    __shared__ __align__(16) float s_h[4][2][NAB];
    int w = threadIdx.x >> 5, l = threadIdx.x & 31;
    int f4 = l * 4;
    float4 bb1 = *(const float4*)&b1[f4];
    float4 bb2 = *(const float4*)&b2[f4];
    int npairs = (Nrows + 1) >> 1;
    for (int pair = blockIdx.x * 4 + w; pair < npairs; pair += gridDim.x * 4) {
        int r0 = pair * 2;
        int r1 = r0 + 1;
        bool has1 = (r1 < Nrows);
        *(float4*)&s_row[w][0][f4] = *(const float4*)&g_agg[(size_t)r0 * NAB + f4];
        *(float4*)&s_row[w][1][f4] = has1 ? *(const float4*)&g_agg[(size_t)r1 * NAB + f4]
                                          : make_float4(0.f, 0.f, 0.f, 0.f);
        __syncwarp();
        float4 a0 = bb1, a1 = bb1;
        #pragma unroll 8
        for (int k = 0; k < NAB; k++) {
            float4 wv = __ldg((const float4*)&W1[k * NAB + f4]);
            float x0 = s_row[w][0][k], x1 = s_row[w][1][k];
            a0.x += x0 * wv.x; a0.y += x0 * wv.y; a0.z += x0 * wv.z; a0.w += x0 * wv.w;
            a1.x += x1 * wv.x; a1.y += x1 * wv.y; a1.z += x1 * wv.z; a1.w += x1 * wv.w;
        }
        s_h[w][0][f4 + 0] = sspf(a0.x); s_h[w][0][f4 + 1] = sspf(a0.y);
        s_h[w][0][f4 + 2] = sspf(a0.z); s_h[w][0][f4 + 3] = sspf(a0.w);
        s_h[w][1][f4 + 0] = sspf(a1.x); s_h[w][1][f4 + 1] = sspf(a1.y);
        s_h[w][1][f4 + 2] = sspf(a1.z); s_h[w][1][f4 + 3] = sspf(a1.w);
        __syncwarp();
        float4 c0 = bb2, c1 = bb2;
        #pragma unroll 8
        for (int j = 0; j < NAB; j++) {
            float4 wv = __ldg((const float4*)&W2[j * NAB + f4]);
            float h0 = s_h[w][0][j], h1v = s_h[w][1][j];
            c0.x += h0 * wv.x;  c0.y += h0 * wv.y;  c0.z += h0 * wv.z;  c0.w += h0 * wv.w;
            c1.x += h1v * wv.x; c1.y += h1v * wv.y; c1.z += h1v * wv.z; c1.w += h1v * wv.w;
        }
        *(float4*)&out[(size_t)r0 * NAB + f4] = c0;
        if (has1) *(float4*)&out[(size_t)r1 * NAB + f4] = c1;
        __syncwarp();
    }
}

// ---------------------------------------------------------------------------
extern "C" void kernel_launch(void* const* d_in, const int* in_sizes, int n_in,
                              void* d_out, int out_size) {
    const float* r     = (const float*)d_in[0];
    const float* e     = (const float*)d_in[1];
    const int*   a     = (const int*)d_in[2];     // int32 on device (JAX x64 off)
    const float* W_df1 = (const float*)d_in[3];
    const float* b_df1 = (const float*)d_in[4];
    const float* W_df2 = (const float*)d_in[5];
    const float* b_df2 = (const float*)d_in[6];
    const float* W_af  = (const float*)d_in[7];
    const float* W_d1  = (const float*)d_in[8];
    const float* b_d1  = (const float*)d_in[9];
    const float* W_d2  = (const float*)d_in[10];
    const float* b_d2  = (const float*)d_in[11];
    float* out = (float*)d_out;

    int N = in_sizes[0] / NAB;
    int E = in_sizes[1];

    void* agg_ptr = nullptr;
    cudaGetSymbolAddress(&agg_ptr, g_agg);
    cudaMemsetAsync(agg_ptr, 0, (size_t)N * NAB * sizeof(float), 0);

    int npairs  = (N + 1) >> 1;
    int grid_rf = (npairs + 3) / 4;
    k_rf<<<grid_rf, 128>>>(r, W_af, N);

    int ntiles = (E + EB - 1) / EB;
    int grid_e = ntiles < 1184 ? ntiles : 1184;
    k_edge<<<grid_e, 128>>>(e, a, W_df1, b_df1, W_df2, b_df2, E);

    k_out<<<grid_rf, 128>>>(W_d1, b_d1, W_d2, b_d2, out, N);
}

// round 3
// speedup vs baseline: 1.8984x; 1.8984x over previous
#include <cuda_runtime.h>
#include <cstdint>

#define NAB       128
#define NG        50
#define NGP       52
#define EB        32
#define MAX_ATOMS 50000

__device__ __align__(16) float g_rf[(size_t)MAX_ATOMS * NAB];
__device__ __align__(16) float g_agg[(size_t)MAX_ATOMS * NAB];

__device__ __forceinline__ float sspf(float x) {
    return fmaxf(x, 0.0f) + log1pf(__expf(-fabsf(x))) - 0.6931471805599453f;
}

// ---- packed f32x2 helpers (sm_100+) ---------------------------------------
__device__ __forceinline__ unsigned long long pk2(float lo, float hi) {
    unsigned long long r;
    asm("mov.b64 %0, {%1, %2};" : "=l"(r) : "f"(lo), "f"(hi));
    return r;
}
__device__ __forceinline__ unsigned long long fma2(unsigned long long a,
                                                   unsigned long long b,
                                                   unsigned long long c) {
    unsigned long long d;
    asm("fma.rn.f32x2 %0, %1, %2, %3;" : "=l"(d) : "l"(a), "l"(b), "l"(c));
    return d;
}
__device__ __forceinline__ float2 up2(unsigned long long v) {
    float2 f;
    asm("mov.b64 {%0, %1}, %2;" : "=f"(f.x), "=f"(f.y) : "l"(v));
    return f;
}

// ---------------------------------------------------------------------------
// rf = r @ W_af  AND zero g_agg rows (fold memset to keep launch count at 4)
// ---------------------------------------------------------------------------
__global__ void __launch_bounds__(128) k_rf(const float* __restrict__ r,
                                            const float* __restrict__ Waf,
                                            int Nrows) {
    __shared__ __align__(16) float s_row[4][2][NAB];
    int w = threadIdx.x >> 5, l = threadIdx.x & 31;
    int f4 = l * 4;
    const float4 z4 = make_float4(0.f, 0.f, 0.f, 0.f);
    int npairs = (Nrows + 1) >> 1;
    for (int pair = blockIdx.x * 4 + w; pair < npairs; pair += gridDim.x * 4) {
        int r0 = pair * 2;
        int r1 = r0 + 1;
        bool has1 = (r1 < Nrows);
        *(float4*)&s_row[w][0][f4] = *(const float4*)&r[(size_t)r0 * NAB + f4];
        *(float4*)&s_row[w][1][f4] = has1 ? *(const float4*)&r[(size_t)r1 * NAB + f4] : z4;
        __syncwarp();
        float4 a0 = z4, a1 = z4;
        #pragma unroll 8
        for (int k = 0; k < NAB; k++) {
            float4 wv = __ldg((const float4*)&Waf[k * NAB + f4]);
            float x0 = s_row[w][0][k], x1 = s_row[w][1][k];
            a0.x += x0 * wv.x; a0.y += x0 * wv.y; a0.z += x0 * wv.z; a0.w += x0 * wv.w;
            a1.x += x1 * wv.x; a1.y += x1 * wv.y; a1.z += x1 * wv.z; a1.w += x1 * wv.w;
        }
        *(float4*)&g_rf[(size_t)r0 * NAB + f4]  = a0;
        *(float4*)&g_agg[(size_t)r0 * NAB + f4] = z4;
        if (has1) {
            *(float4*)&g_rf[(size_t)r1 * NAB + f4]  = a1;
            *(float4*)&g_agg[(size_t)r1 * NAB + f4] = z4;
        }
        __syncwarp();
    }
}

// ---------------------------------------------------------------------------
// Fused edge kernel. 32 edges/tile, 256 threads.
// ---------------------------------------------------------------------------
__global__ void __launch_bounds__(256) k_edge(const float* __restrict__ e_arr,
                                              const int* __restrict__ a_arr,
                                              const float* __restrict__ W1g,
                                              const float* __restrict__ b1g,
                                              const float* __restrict__ W2g,
                                              const float* __restrict__ b2g,
                                              int E) {
    __shared__ __align__(16) float sW1[NG * NGP];    // [i][j] padded to 52
    __shared__ __align__(16) float sb1[NGP];
    __shared__ __align__(16) float sW2[NG * NAB];    // [j][f]
    __shared__ __align__(16) float sb2[NAB];
    __shared__ __align__(16) float s_g[EB * NGP];    // [edge][i]
    __shared__ __align__(16) float s_h1[NG * EB];    // [j][edge]
    __shared__ __align__(16) float s_ev[EB];
    __shared__ int s_src[EB], s_dst[EB];

    const int tid = threadIdx.x;

    // one-time staging
    for (int idx = tid; idx < NG * NGP; idx += 256) {
        int i = idx / NGP, j = idx % NGP;
        sW1[idx] = (j < NG) ? W1g[i * NG + j] : 0.0f;
    }
    if (tid < NGP) sb1[tid] = (tid < NG) ? b1g[tid] : 0.0f;
    for (int idx = tid; idx < NG * NAB; idx += 256) sW2[idx] = W2g[idx];
    if (tid < NAB) sb2[tid] = b2g[tid];

    const float kWidth = 5.0f / 49.0f;
    const float kCoeff = -0.5f / (kWidth * kWidth);

    // phase-B assignment: 16 edge-pairs x 13 j-groups = 208 active threads
    const int jq    = tid % 13;
    const int epair = tid / 13;
    const int j4    = jq * 4;
    const bool actB = (tid < 208);

    // phase-C assignment: fgroup x edge-group
    const int fg = tid & 31;          // feature group 0..31 -> feats 4*fg
    const int eg = tid >> 5;          // 0..7 -> edges 4*eg .. 4*eg+3
    const int fb = fg * 4;

    const int ntiles = (E + EB - 1) / EB;
    for (int tile = blockIdx.x; tile < ntiles; tile += gridDim.x) {
        const int e0 = tile * EB;
        __syncthreads();   // protect smem reuse (covers staging on iter 0)
        if (tid < EB) {
            int ei = e0 + tid;
            if (ei < E) {
                s_ev[tid]  = e_arr[ei];
                s_src[tid] = a_arr[2 * (size_t)ei];
                s_dst[tid] = a_arr[2 * (size_t)ei + 1];
            } else {
                s_ev[tid] = 0.0f; s_src[tid] = -1; s_dst[tid] = -1;
            }
        }
        __syncthreads();

        // phase A: Gaussians  (32*50 = 1600 items)
        for (int it = tid; it < EB * NG; it += 256) {
            int ee = it / NG;
            int i  = it - ee * NG;
            float d = s_ev[ee] - (float)i * kWidth;
            s_g[ee * NGP + i] = __expf(kCoeff * d * d);
        }
        __syncthreads();

        // phase B: h1 = ssp(g @ W1 + b1), 2 edges x 4 j per thread
        if (actB) {
            const int ea = epair * 2, eb2 = ea + 1;
            float4 a0 = make_float4(sb1[j4], sb1[j4 + 1], sb1[j4 + 2], sb1[j4 + 3]);
            float4 a1 = a0;
            const float* gA = &s_g[ea * NGP];
            const float* gB = &s_g[eb2 * NGP];
            #pragma unroll 10
            for (int i = 0; i < NG; i++) {
                float4 wv = *(const float4*)&sW1[i * NGP + j4];
                float x0 = gA[i], x1 = gB[i];
                a0.x += x0 * wv.x; a0.y += x0 * wv.y; a0.z += x0 * wv.z; a0.w += x0 * wv.w;
                a1.x += x1 * wv.x; a1.y += x1 * wv.y; a1.z += x1 * wv.z; a1.w += x1 * wv.w;
            }
            float* p0 = (float*)&a0;
            float* p1 = (float*)&a1;
            #pragma unroll
            for (int k = 0; k < 4; k++) {
                int j = j4 + k;
                if (j < NG) {
                    s_h1[j * EB + ea]  = sspf(p0[k]);
                    s_h1[j * EB + eb2] = sspf(p1[k]);
                }
            }
        }
        __syncthreads();

        // phase C: ef = h1 @ W2 + b2 (packed f32x2), gather rf, RED atomics
        {
            unsigned long long b01 = pk2(sb2[fb],     sb2[fb + 1]);
            unsigned long long b23 = pk2(sb2[fb + 2], sb2[fb + 3]);
            unsigned long long acc0a = b01, acc0b = b23;   // edge 4eg+0
            unsigned long long acc1a = b01, acc1b = b23;   // edge 4eg+1
            unsigned long long acc2a = b01, acc2b = b23;   // edge 4eg+2
            unsigned long long acc3a = b01, acc3b = b23;   // edge 4eg+3
            const float* h1p = &s_h1[4 * eg];
            #pragma unroll 5
            for (int j = 0; j < NG; j++) {
                float4 wv = *(const float4*)&sW2[j * NAB + fb];
                unsigned long long w01 = pk2(wv.x, wv.y);
                unsigned long long w23 = pk2(wv.z, wv.w);
                float4 hv = *(const float4*)&h1p[j * EB];   // broadcast within warp
                unsigned long long h0 = pk2(hv.x, hv.x);
                unsigned long long h1 = pk2(hv.y, hv.y);
                unsigned long long h2 = pk2(hv.z, hv.z);
                unsigned long long h3 = pk2(hv.w, hv.w);
                acc0a = fma2(w01, h0, acc0a); acc0b = fma2(w23, h0, acc0b);
                acc1a = fma2(w01, h1, acc1a); acc1b = fma2(w23, h1, acc1b);
                acc2a = fma2(w01, h2, acc2a); acc2b = fma2(w23, h2, acc2b);
                acc3a = fma2(w01, h3, acc3a); acc3b = fma2(w23, h3, acc3b);
            }
            unsigned long long accs[4][2] = {{acc0a, acc0b}, {acc1a, acc1b},
                                             {acc2a, acc2b}, {acc3a, acc3b}};
            #pragma unroll
            for (int k = 0; k < 4; k++) {
                int ee = 4 * eg + k;
                int s = s_src[ee], d = s_dst[ee];
                if (s >= 0) {
                    float2 lo = up2(accs[k][0]);
                    float2 hi = up2(accs[k][1]);
                    float4 ef = make_float4(lo.x, lo.y, hi.x, hi.y);
                    float4 rs = __ldg((const float4*)&g_rf[(size_t)s * NAB + fb]);
                    float4 rd = __ldg((const float4*)&g_rf[(size_t)d * NAB + fb]);
                    float4 m1 = make_float4(rs.x * ef.x, rs.y * ef.y, rs.z * ef.z, rs.w * ef.w);
                    float4 m2 = make_float4(rd.x * ef.x, rd.y * ef.y, rd.z * ef.z, rd.w * ef.w);
                    atomicAdd((float4*)&g_agg[(size_t)d * NAB + fb], m1);
                    atomicAdd((float4*)&g_agg[(size_t)s * NAB + fb], m2);
                }
            }
        }
    }
}

// ---------------------------------------------------------------------------
// out = ssp(agg @ W_d1 + b_d1) @ W_d2 + b_d2
// ---------------------------------------------------------------------------
__global__ void __launch_bounds__(128) k_out(const float* __restrict__ W1,
                                             const float* __restrict__ b1,
                                             const float* __restrict__ W2,
                                             const float* __restrict__ b2,
                                             float* __restrict__ out,
                                             int Nrows) {
    __shared__ __align__(16) float s_row[4][2][NAB];
    __shared__ __align__(16) float s_h[4][2][NAB];
    int w = threadIdx.x >> 5, l = threadIdx.x & 31;
    int f4 = l * 4;
    float4 bb1 = *(const float4*)&b1[f4];
    float4 bb2 = *(const float4*)&b2[f4];
    int npairs = (Nrows + 1) >> 1;
    for (int pair = blockIdx.x * 4 + w; pair < npairs; pair += gridDim.x * 4) {
        int r0 = pair * 2;
        int r1 = r0 + 1;
        bool has1 = (r1 < Nrows);
        *(float4*)&s_row[w][0][f4] = *(const float4*)&g_agg[(size_t)r0 * NAB + f4];
        *(float4*)&s_row[w][1][f4] = has1 ? *(const float4*)&g_agg[(size_t)r1 * NAB + f4]
                                          : make_float4(0.f, 0.f, 0.f, 0.f);
        __syncwarp();
        float4 a0 = bb1, a1 = bb1;
        #pragma unroll 8
        for (int k = 0; k < NAB; k++) {
            float4 wv = __ldg((const float4*)&W1[k * NAB + f4]);
            float x0 = s_row[w][0][k], x1 = s_row[w][1][k];
            a0.x += x0 * wv.x; a0.y += x0 * wv.y; a0.z += x0 * wv.z; a0.w += x0 * wv.w;
            a1.x += x1 * wv.x; a1.y += x1 * wv.y; a1.z += x1 * wv.z; a1.w += x1 * wv.w;
        }
        s_h[w][0][f4 + 0] = sspf(a0.x); s_h[w][0][f4 + 1] = sspf(a0.y);
        s_h[w][0][f4 + 2] = sspf(a0.z); s_h[w][0][f4 + 3] = sspf(a0.w);
        s_h[w][1][f4 + 0] = sspf(a1.x); s_h[w][1][f4 + 1] = sspf(a1.y);
        s_h[w][1][f4 + 2] = sspf(a1.z); s_h[w][1][f4 + 3] = sspf(a1.w);
        __syncwarp();
        float4 c0 = bb2, c1 = bb2;
        #pragma unroll 8
        for (int j = 0; j < NAB; j++) {
            float4 wv = __ldg((const float4*)&W2[j * NAB + f4]);
            float h0 = s_h[w][0][j], h1v = s_h[w][1][j];
            c0.x += h0 * wv.x;  c0.y += h0 * wv.y;  c0.z += h0 * wv.z;  c0.w += h0 * wv.w;
            c1.x += h1v * wv.x; c1.y += h1v * wv.y; c1.z += h1v * wv.z; c1.w += h1v * wv.w;
        }
        *(float4*)&out[(size_t)r0 * NAB + f4] = c0;
        if (has1) *(float4*)&out[(size_t)r1 * NAB + f4] = c1;
        __syncwarp();
    }
}

__global__ void k_noop() {}

// ---------------------------------------------------------------------------
extern "C" void kernel_launch(void* const* d_in, const int* in_sizes, int n_in,
                              void* d_out, int out_size) {
    const float* r     = (const float*)d_in[0];
    const float* e     = (const float*)d_in[1];
    const int*   a     = (const int*)d_in[2];
    const float* W_df1 = (const float*)d_in[3];
    const float* b_df1 = (const float*)d_in[4];
    const float* W_df2 = (const float*)d_in[5];
    const float* b_df2 = (const float*)d_in[6];
    const float* W_af  = (const float*)d_in[7];
    const float* W_d1  = (const float*)d_in[8];
    const float* b_d1  = (const float*)d_in[9];
    const float* W_d2  = (const float*)d_in[10];
    const float* b_d2  = (const float*)d_in[11];
    float* out = (float*)d_out;

    int N = in_sizes[0] / NAB;
    int E = in_sizes[1];

    int npairs  = (N + 1) >> 1;
    int grid_rf = (npairs + 3) / 4;
    k_rf<<<grid_rf, 128>>>(r, W_af, N);

    int ntiles = (E + EB - 1) / EB;
    int grid_e = ntiles < 592 ? ntiles : 592;
    k_edge<<<grid_e, 256>>>(e, a, W_df1, b_df1, W_df2, b_df2, E);

    k_out<<<grid_rf, 128>>>(W_d1, b_d1, W_d2, b_d2, out, N);

    k_noop<<<1, 32>>>();   // keeps 4 launches/call: ncu -s5 lands on k_edge
}

// round 4
// speedup vs baseline: 2.0519x; 1.0808x over previous
#include <cuda_runtime.h>
#include <cstdint>

#define NAB       128
#define NG        50
#define NGP       52
#define EB        64
#define MAX_ATOMS 50000

typedef unsigned long long ull;

__device__ __align__(16) float g_rf[(size_t)MAX_ATOMS * NAB];
__device__ __align__(16) float g_agg[(size_t)MAX_ATOMS * NAB];

__device__ __forceinline__ float sspf(float x) {
    return fmaxf(x, 0.0f) + log1pf(__expf(-fabsf(x))) - 0.6931471805599453f;
}

// ---- packed f32x2 helpers (sm_100+; ptxas never emits these from C++) -----
__device__ __forceinline__ ull pk2(float lo, float hi) {
    ull r; asm("mov.b64 %0, {%1, %2};" : "=l"(r) : "f"(lo), "f"(hi)); return r;
}
__device__ __forceinline__ ull fma2(ull a, ull b, ull c) {
    ull d; asm("fma.rn.f32x2 %0, %1, %2, %3;" : "=l"(d) : "l"(a), "l"(b), "l"(c));
    return d;
}
__device__ __forceinline__ float2 up2(ull v) {
    float2 f; asm("mov.b64 {%0, %1}, %2;" : "=f"(f.x), "=f"(f.y) : "l"(v));
    return f;
}

// ---------------------------------------------------------------------------
// rf = r @ W_af  AND zero g_agg rows
// ---------------------------------------------------------------------------
__global__ void __launch_bounds__(128) k_rf(const float* __restrict__ r,
                                            const float* __restrict__ Waf,
                                            int Nrows) {
    __shared__ __align__(16) float s_row[4][2][NAB];
    int w = threadIdx.x >> 5, l = threadIdx.x & 31;
    int f4 = l * 4;
    const float4 z4 = make_float4(0.f, 0.f, 0.f, 0.f);
    int npairs = (Nrows + 1) >> 1;
    for (int pair = blockIdx.x * 4 + w; pair < npairs; pair += gridDim.x * 4) {
        int r0 = pair * 2, r1 = r0 + 1;
        bool has1 = (r1 < Nrows);
        *(float4*)&s_row[w][0][f4] = *(const float4*)&r[(size_t)r0 * NAB + f4];
        *(float4*)&s_row[w][1][f4] = has1 ? *(const float4*)&r[(size_t)r1 * NAB + f4] : z4;
        __syncwarp();
        float4 a0 = z4, a1 = z4;
        #pragma unroll 8
        for (int k = 0; k < NAB; k++) {
            float4 wv = __ldg((const float4*)&Waf[k * NAB + f4]);
            float x0 = s_row[w][0][k], x1 = s_row[w][1][k];
            a0.x += x0 * wv.x; a0.y += x0 * wv.y; a0.z += x0 * wv.z; a0.w += x0 * wv.w;
            a1.x += x1 * wv.x; a1.y += x1 * wv.y; a1.z += x1 * wv.z; a1.w += x1 * wv.w;
        }
        *(float4*)&g_rf[(size_t)r0 * NAB + f4]  = a0;
        *(float4*)&g_agg[(size_t)r0 * NAB + f4] = z4;
        if (has1) {
            *(float4*)&g_rf[(size_t)r1 * NAB + f4]  = a1;
            *(float4*)&g_agg[(size_t)r1 * NAB + f4] = z4;
        }
        __syncwarp();
    }
}

// ---------------------------------------------------------------------------
// Fused edge kernel: 64 edges/tile, 256 threads, f32x2 throughout.
// ---------------------------------------------------------------------------
__global__ void __launch_bounds__(256) k_edge(const float* __restrict__ e_arr,
                                              const int* __restrict__ a_arr,
                                              const float* __restrict__ W1g,
                                              const float* __restrict__ b1g,
                                              const float* __restrict__ W2g,
                                              const float* __restrict__ b2g,
                                              int E) {
    __shared__ __align__(16) float sW1[NG * NGP];    // [i][j], padded (pad cols zero)
    __shared__ __align__(16) float sb1[NGP];
    __shared__ __align__(16) float sW2[NG * NAB];    // [j][f]
    __shared__ __align__(16) float sb2[NAB];
    __shared__ __align__(16) float s_g[EB * NGP];    // [edge][i]
    __shared__ __align__(16) float s_h1[NG * EB];    // [j][edge]
    __shared__ __align__(16) float s_ev[EB];
    __shared__ int s_src[EB], s_dst[EB];

    const int tid = threadIdx.x;

    // one-time staging
    for (int idx = tid; idx < NG * NGP; idx += 256) {
        int i = idx / NGP, j = idx % NGP;
        sW1[idx] = (j < NG) ? W1g[i * NG + j] : 0.0f;
    }
    if (tid < NGP) sb1[tid] = (tid < NG) ? b1g[tid] : 0.0f;
    for (int idx = tid; idx < NG * NAB; idx += 256) sW2[idx] = W2g[idx];
    if (tid < NAB) sb2[tid] = b2g[tid];

    const float kWidth = 5.0f / 49.0f;
    const float kCoeff = -0.5f / (kWidth * kWidth);

    // phase-B mapping: 16 quads x 13 j-groups = 208 active threads
    const int q    = tid / 13;           // edge quad 0..15 -> edges 4q..4q+3
    const int jq   = tid % 13;
    const int j4   = jq * 4;
    const bool actB = (tid < 208);

    // phase-C mapping: warp w -> edges 8w..8w+7; lane -> features 4*lane
    const int lane = tid & 31;
    const int wrp  = tid >> 5;
    const int fb   = lane * 4;
    const int ebC  = wrp * 8;

    const int ntiles = (E + EB - 1) / EB;
    for (int tile = blockIdx.x; tile < ntiles; tile += gridDim.x) {
        const int e0 = tile * EB;
        __syncthreads();   // protects smem reuse; covers staging on first iter
        if (tid < EB) {
            int ei = e0 + tid;
            if (ei < E) {
                s_ev[tid]  = e_arr[ei];
                s_src[tid] = a_arr[2 * (size_t)ei];
                s_dst[tid] = a_arr[2 * (size_t)ei + 1];
            } else {
                s_ev[tid] = 0.0f; s_src[tid] = -1; s_dst[tid] = -1;
            }
        }
        __syncthreads();

        // phase A: Gaussians  (64*50 = 3200 items)
        for (int it = tid; it < EB * NG; it += 256) {
            int ee = it / NG;
            int i  = it - ee * NG;
            float d = s_ev[ee] - (float)i * kWidth;
            s_g[ee * NGP + i] = __expf(kCoeff * d * d);
        }
        __syncthreads();

        // phase B: h1 = ssp(g @ W1 + b1); 4 edges x 4 j per thread, f32x2
        if (actB) {
            const int eb4 = q * 4;
            ull b01 = pk2(sb1[j4],     sb1[j4 + 1]);
            ull b23 = pk2(sb1[j4 + 2], sb1[j4 + 3]);
            ull a01_0 = b01, a23_0 = b23;
            ull a01_1 = b01, a23_1 = b23;
            ull a01_2 = b01, a23_2 = b23;
            ull a01_3 = b01, a23_3 = b23;
            const float* g0 = &s_g[(eb4 + 0) * NGP];
            const float* g1 = &s_g[(eb4 + 1) * NGP];
            const float* g2 = &s_g[(eb4 + 2) * NGP];
            const float* g3 = &s_g[(eb4 + 3) * NGP];
            #pragma unroll 5
            for (int i = 0; i < NG; i++) {
                ulonglong2 wv = *(const ulonglong2*)&sW1[i * NGP + j4];
                ull h0 = pk2(g0[i], g0[i]);
                a01_0 = fma2(wv.x, h0, a01_0); a23_0 = fma2(wv.y, h0, a23_0);
                ull h1 = pk2(g1[i], g1[i]);
                a01_1 = fma2(wv.x, h1, a01_1); a23_1 = fma2(wv.y, h1, a23_1);
                ull h2 = pk2(g2[i], g2[i]);
                a01_2 = fma2(wv.x, h2, a01_2); a23_2 = fma2(wv.y, h2, a23_2);
                ull h3 = pk2(g3[i], g3[i]);
                a01_3 = fma2(wv.x, h3, a01_3); a23_3 = fma2(wv.y, h3, a23_3);
            }
            ull va[4][2] = {{a01_0, a23_0}, {a01_1, a23_1}, {a01_2, a23_2}, {a01_3, a23_3}};
            #pragma unroll
            for (int k = 0; k < 4; k++) {
                float2 v01 = up2(va[k][0]);
                float2 v23 = up2(va[k][1]);
                int ee = eb4 + k;
                s_h1[(j4 + 0) * EB + ee] = sspf(v01.x);
                s_h1[(j4 + 1) * EB + ee] = sspf(v01.y);
                if (j4 + 2 < NG) s_h1[(j4 + 2) * EB + ee] = sspf(v23.x);
                if (j4 + 3 < NG) s_h1[(j4 + 3) * EB + ee] = sspf(v23.y);
            }
        }
        __syncthreads();

        // phase C: ef = h1 @ W2 + b2; 8 edges x 4 features/thread, f32x2
        {
            ulonglong2 bb = *(const ulonglong2*)&sb2[fb];
            ull acc[8][2];
            #pragma unroll
            for (int k = 0; k < 8; k++) { acc[k][0] = bb.x; acc[k][1] = bb.y; }
            #pragma unroll 2
            for (int j = 0; j < NG; j++) {
                ulonglong2 wv = *(const ulonglong2*)&sW2[j * NAB + fb];
                float4 ha = *(const float4*)&s_h1[j * EB + ebC];       // broadcast
                float4 hb = *(const float4*)&s_h1[j * EB + ebC + 4];   // broadcast
                ull h;
                h = pk2(ha.x, ha.x); acc[0][0] = fma2(wv.x, h, acc[0][0]); acc[0][1] = fma2(wv.y, h, acc[0][1]);
                h = pk2(ha.y, ha.y); acc[1][0] = fma2(wv.x, h, acc[1][0]); acc[1][1] = fma2(wv.y, h, acc[1][1]);
                h = pk2(ha.z, ha.z); acc[2][0] = fma2(wv.x, h, acc[2][0]); acc[2][1] = fma2(wv.y, h, acc[2][1]);
                h = pk2(ha.w, ha.w); acc[3][0] = fma2(wv.x, h, acc[3][0]); acc[3][1] = fma2(wv.y, h, acc[3][1]);
                h = pk2(hb.x, hb.x); acc[4][0] = fma2(wv.x, h, acc[4][0]); acc[4][1] = fma2(wv.y, h, acc[4][1]);
                h = pk2(hb.y, hb.y); acc[5][0] = fma2(wv.x, h, acc[5][0]); acc[5][1] = fma2(wv.y, h, acc[5][1]);
                h = pk2(hb.z, hb.z); acc[6][0] = fma2(wv.x, h, acc[6][0]); acc[6][1] = fma2(wv.y, h, acc[6][1]);
                h = pk2(hb.w, hb.w); acc[7][0] = fma2(wv.x, h, acc[7][0]); acc[7][1] = fma2(wv.y, h, acc[7][1]);
            }
            #pragma unroll
            for (int k = 0; k < 8; k++) {
                int ee = ebC + k;
                int s = s_src[ee], d = s_dst[ee];
                if (s >= 0) {
                    float2 lo = up2(acc[k][0]);
                    float2 hi = up2(acc[k][1]);
                    float4 ef = make_float4(lo.x, lo.y, hi.x, hi.y);
                    float4 rs = __ldg((const float4*)&g_rf[(size_t)s * NAB + fb]);
                    float4 rd = __ldg((const float4*)&g_rf[(size_t)d * NAB + fb]);
                    float4 m1 = make_float4(rs.x * ef.x, rs.y * ef.y, rs.z * ef.z, rs.w * ef.w);
                    float4 m2 = make_float4(rd.x * ef.x, rd.y * ef.y, rd.z * ef.z, rd.w * ef.w);
                    atomicAdd((float4*)&g_agg[(size_t)d * NAB + fb], m1);
                    atomicAdd((float4*)&g_agg[(size_t)s * NAB + fb], m2);
                }
            }
        }
    }
}

// ---------------------------------------------------------------------------
// out = ssp(agg @ W_d1 + b_d1) @ W_d2 + b_d2
// ---------------------------------------------------------------------------
__global__ void __launch_bounds__(128) k_out(const float* __restrict__ W1,
                                             const float* __restrict__ b1,
                                             const float* __restrict__ W2,
                                             const float* __restrict__ b2,
                                             float* __restrict__ out,
                                             int Nrows) {
    __shared__ __align__(16) float s_row[4][2][NAB];
    __shared__ __align__(16) float s_h[4][2][NAB];
    int w = threadIdx.x >> 5, l = threadIdx.x & 31;
    int f4 = l * 4;
    float4 bb1 = *(const float4*)&b1[f4];
    float4 bb2 = *(const float4*)&b2[f4];
    int npairs = (Nrows + 1) >> 1;
    for (int pair = blockIdx.x * 4 + w; pair < npairs; pair += gridDim.x * 4) {
        int r0 = pair * 2, r1 = r0 + 1;
        bool has1 = (r1 < Nrows);
        *(float4*)&s_row[w][0][f4] = *(const float4*)&g_agg[(size_t)r0 * NAB + f4];
        *(float4*)&s_row[w][1][f4] = has1 ? *(const float4*)&g_agg[(size_t)r1 * NAB + f4]
                                          : make_float4(0.f, 0.f, 0.f, 0.f);
        __syncwarp();
        float4 a0 = bb1, a1 = bb1;
        #pragma unroll 8
        for (int k = 0; k < NAB; k++) {
            float4 wv = __ldg((const float4*)&W1[k * NAB + f4]);
            float x0 = s_row[w][0][k], x1 = s_row[w][1][k];
            a0.x += x0 * wv.x; a0.y += x0 * wv.y; a0.z += x0 * wv.z; a0.w += x0 * wv.w;
            a1.x += x1 * wv.x; a1.y += x1 * wv.y; a1.z += x1 * wv.z; a1.w += x1 * wv.w;
        }
        s_h[w][0][f4 + 0] = sspf(a0.x); s_h[w][0][f4 + 1] = sspf(a0.y);
        s_h[w][0][f4 + 2] = sspf(a0.z); s_h[w][0][f4 + 3] = sspf(a0.w);
        s_h[w][1][f4 + 0] = sspf(a1.x); s_h[w][1][f4 + 1] = sspf(a1.y);
        s_h[w][1][f4 + 2] = sspf(a1.z); s_h[w][1][f4 + 3] = sspf(a1.w);
        __syncwarp();
        float4 c0 = bb2, c1 = bb2;
        #pragma unroll 8
        for (int j = 0; j < NAB; j++) {
            float4 wv = __ldg((const float4*)&W2[j * NAB + f4]);
            float h0 = s_h[w][0][j], h1v = s_h[w][1][j];
            c0.x += h0 * wv.x;  c0.y += h0 * wv.y;  c0.z += h0 * wv.z;  c0.w += h0 * wv.w;
            c1.x += h1v * wv.x; c1.y += h1v * wv.y; c1.z += h1v * wv.z; c1.w += h1v * wv.w;
        }
        *(float4*)&out[(size_t)r0 * NAB + f4] = c0;
        if (has1) *(float4*)&out[(size_t)r1 * NAB + f4] = c1;
        __syncwarp();
    }
}

__global__ void k_noop() {}

// ---------------------------------------------------------------------------
extern "C" void kernel_launch(void* const* d_in, const int* in_sizes, int n_in,
                              void* d_out, int out_size) {
    const float* r     = (const float*)d_in[0];
    const float* e     = (const float*)d_in[1];
    const int*   a     = (const int*)d_in[2];
    const float* W_df1 = (const float*)d_in[3];
    const float* b_df1 = (const float*)d_in[4];
    const float* W_df2 = (const float*)d_in[5];
    const float* b_df2 = (const float*)d_in[6];
    const float* W_af  = (const float*)d_in[7];
    const float* W_d1  = (const float*)d_in[8];
    const float* b_d1  = (const float*)d_in[9];
    const float* W_d2  = (const float*)d_in[10];
    const float* b_d2  = (const float*)d_in[11];
    float* out = (float*)d_out;

    int N = in_sizes[0] / NAB;
    int E = in_sizes[1];

    int npairs  = (N + 1) >> 1;
    int grid_rf = (npairs + 3) / 4;

    // 6 launches/iter, k_edge at position 3: profiled launch index L≡3 (mod 12)
    k_rf<<<grid_rf, 128>>>(r, W_af, N);                    // 0
    k_noop<<<1, 32>>>();                                   // 1
    k_noop<<<1, 32>>>();                                   // 2
    int ntiles = (E + EB - 1) / EB;
    int grid_e = ntiles < 444 ? ntiles : 444;
    k_edge<<<grid_e, 256>>>(e, a, W_df1, b_df1, W_df2, b_df2, E);   // 3
    k_out<<<grid_rf, 128>>>(W_d1, b_d1, W_d2, b_d2, out, N);        // 4
    k_noop<<<1, 32>>>();                                   // 5
}